// round 5
// baseline (speedup 1.0000x reference)
#include <cuda_runtime.h>

// SSIM, 7x7 VALID box, 128 x 384x384 fp32 pairs -> scalar mean.
//
// v5: fully packed f32x2 pipeline.
//  - 4 cols/lane warp strips (LDG.128), vertical sliding sums packed.
//  - XX+YY merged into one quantity Z (SSIM only needs vx+vy).
//  - Horizontal 7-sums in f32x2: aligned pairs E + register-aliased shifted
//    pairs D; 9 packed adds + 6 shuffles per quantity for 4 outputs.
//  - SSIM evaluated packed; masks packed; per-warp -> per-CTA -> last-CTA
//    global reduction in ONE kernel (deterministic order).

#define IMG_H 384
#define IMG_W 384
#define OUT_W 378
#define OUT_H 378
#define NIMG  128
#define NSTRIP 4
#define NBAND  6
#define BAND_OUT 63
#define WARPS_PER_CTA 8
#define WARPS_TOTAL (NIMG * NSTRIP * NBAND)      // 3072
#define NCTA (WARPS_TOTAL / WARPS_PER_CTA)       // 384

__device__ float g_cta[NCTA];
__device__ unsigned int g_done = 0;

typedef unsigned long long u64;
static __device__ __forceinline__ u64 pk2(float lo, float hi) {
    u64 r; asm("mov.b64 %0,{%1,%2};" : "=l"(r) : "f"(lo), "f"(hi)); return r;
}
static __device__ __forceinline__ void upk2(float& lo, float& hi, u64 v) {
    asm("mov.b64 {%0,%1},%2;" : "=f"(lo), "=f"(hi) : "l"(v));
}
static __device__ __forceinline__ u64 add2(u64 a, u64 b) {
    u64 d; asm("add.rn.f32x2 %0,%1,%2;" : "=l"(d) : "l"(a), "l"(b)); return d;
}
static __device__ __forceinline__ u64 mul2(u64 a, u64 b) {
    u64 d; asm("mul.rn.f32x2 %0,%1,%2;" : "=l"(d) : "l"(a), "l"(b)); return d;
}
static __device__ __forceinline__ u64 fma2(u64 a, u64 b, u64 c) {
    u64 d; asm("fma.rn.f32x2 %0,%1,%2,%3;" : "=l"(d) : "l"(a), "l"(b), "l"(c)); return d;
}
static __device__ __forceinline__ u64 neg2(u64 a) {
    return a ^ 0x8000000080000000ULL;
}

// Packed horizontal 7-sum: q01=(v0,v1), q23=(v2,v3) per lane; lane l's
// outputs 4l+j need v_j..v_{j+6} where v4..v9 come from lanes l+1, l+2.
// Wlo=(W0,W1), Whi=(W2,W3).
#define HPACK(q01, q23, Wlo, Whi)                                          \
    {                                                                      \
        float v0, v1, v2, v3;                                              \
        upk2(v0, v1, q01); upk2(v2, v3, q23);                              \
        float v4 = __shfl_down_sync(0xffffffffu, v0, 1);                   \
        float v5 = __shfl_down_sync(0xffffffffu, v1, 1);                   \
        float v6 = __shfl_down_sync(0xffffffffu, v2, 1);                   \
        float v7 = __shfl_down_sync(0xffffffffu, v3, 1);                   \
        float v8 = __shfl_down_sync(0xffffffffu, v0, 2);                   \
        float v9 = __shfl_down_sync(0xffffffffu, v1, 2);                   \
        u64 E2 = pk2(v4, v5), E3 = pk2(v6, v7), E4 = pk2(v8, v9);          \
        u64 D0 = pk2(v1, v2), D1 = pk2(v3, v4);                            \
        u64 D2 = pk2(v5, v6), D3 = pk2(v7, v8);                            \
        u64 SE = add2(q23, add2(E2, E3));                                  \
        u64 SD = add2(D1, D2);                                             \
        Wlo = add2(add2(q01, SE), add2(D0, SD));                           \
        Whi = add2(add2(SE, E4), add2(SD, D3));                            \
    }

__global__ __launch_bounds__(WARPS_PER_CTA * 32)
void ssim_v5_kernel(const float* __restrict__ pred,
                    const float* __restrict__ actual,
                    float* __restrict__ out) {
    const int gtid = blockIdx.x * blockDim.x + threadIdx.x;
    const int W    = gtid >> 5;
    const int lane = gtid & 31;
    const int wid  = threadIdx.x >> 5;

    const int img   = W / (NSTRIP * NBAND);
    const int rem   = W - img * (NSTRIP * NBAND);
    const int band  = rem / NSTRIP;
    const int strip = rem - band * NSTRIP;

    // strips: [0,96) [96,192) [192,284) [284,378)
    int base = strip * 96;          if (strip == 3) base = 284;
    int send = base + 96;           if (strip == 2) send = 284;
    if (strip == 3) send = 378;

    int cs = base + 4 * lane;
    if (cs > IMG_W - 4) cs = IMG_W - 4;

    const int r0 = band * BAND_OUT;

    const float* __restrict__ xp = pred   + (size_t)img * IMG_H * IMG_W;
    const float* __restrict__ yp = actual + (size_t)img * IMG_H * IMG_W;

    const int oc = base + 4 * lane;
    const u64 m01 = pk2((oc + 0 < send) ? 1.f : 0.f, (oc + 1 < send) ? 1.f : 0.f);
    const u64 m23 = pk2((oc + 2 < send) ? 1.f : 0.f, (oc + 3 < send) ? 1.f : 0.f);

    // packed vertical sliding sums: X, Y, Z = XX+YY, XY
    u64 X01 = 0, X23 = 0, Y01 = 0, Y23 = 0;
    u64 Z01 = 0, Z23 = 0, XY01 = 0, XY23 = 0;

    #pragma unroll 1
    for (int k = 0; k < 6; ++k) {
        float4 a = *(const float4*)(xp + (size_t)(r0 + k) * IMG_W + cs);
        float4 b = *(const float4*)(yp + (size_t)(r0 + k) * IMG_W + cs);
        u64 ax01 = pk2(a.x, a.y), ax23 = pk2(a.z, a.w);
        u64 ay01 = pk2(b.x, b.y), ay23 = pk2(b.z, b.w);
        X01 = add2(X01, ax01);  X23 = add2(X23, ax23);
        Y01 = add2(Y01, ay01);  Y23 = add2(Y23, ay23);
        Z01 = fma2(ax01, ax01, fma2(ay01, ay01, Z01));
        Z23 = fma2(ax23, ax23, fma2(ay23, ay23, Z23));
        XY01 = fma2(ax01, ay01, XY01);  XY23 = fma2(ax23, ay23, XY23);
    }

    float4 pfx = *(const float4*)(xp + (size_t)(r0 + 6) * IMG_W + cs);
    float4 pfy = *(const float4*)(yp + (size_t)(r0 + 6) * IMG_W + cs);

    const float s1   = 1.0f / 49.0f;
    const float covn = 49.0f / 48.0f;
    const u64 c_ns1 = pk2(-s1, -s1);
    const u64 c_kn1 = pk2(2.f * s1 * s1, 2.f * s1 * s1);
    const u64 c_ks2 = pk2(s1 * s1, s1 * s1);
    const u64 c_kcv = pk2(covn * s1, covn * s1);
    const u64 c_kc2 = pk2(2.f * covn * s1, 2.f * covn * s1);
    const u64 c_C1  = pk2(1e-4f, 1e-4f);
    const u64 c_C2  = pk2(9e-4f, 9e-4f);

    u64 accA = 0, accB = 0;   // packed accumulators (lo-pair, hi-pair)

    #pragma unroll 1
    for (int r = 0; r < BAND_OUT; ++r) {
        // admit prefetched row (input r0+r+6)
        {
            u64 ax01 = pk2(pfx.x, pfx.y), ax23 = pk2(pfx.z, pfx.w);
            u64 ay01 = pk2(pfy.x, pfy.y), ay23 = pk2(pfy.z, pfy.w);
            X01 = add2(X01, ax01);  X23 = add2(X23, ax23);
            Y01 = add2(Y01, ay01);  Y23 = add2(Y23, ay23);
            Z01 = fma2(ax01, ax01, fma2(ay01, ay01, Z01));
            Z23 = fma2(ax23, ax23, fma2(ay23, ay23, Z23));
            XY01 = fma2(ax01, ay01, XY01);  XY23 = fma2(ax23, ay23, XY23);
        }
        // prefetch next row (clamped)
        {
            int nr = min(r0 + r + 7, IMG_H - 1);
            pfx = *(const float4*)(xp + (size_t)nr * IMG_W + cs);
            pfy = *(const float4*)(yp + (size_t)nr * IMG_W + cs);
        }

        // horizontal packed 7-sums for 4 quantities
        u64 WXl, WXh, WYl, WYh, WZl, WZh, WXYl, WXYh;
        HPACK(X01,  X23,  WXl,  WXh);
        HPACK(Y01,  Y23,  WYl,  WYh);
        HPACK(Z01,  Z23,  WZl,  WZh);
        HPACK(XY01, XY23, WXYl, WXYh);

        // SSIM, packed halves
        {
            u64 p01 = mul2(WXl, WYl);
            u64 p00 = mul2(WXl, WXl);
            u64 p11 = mul2(WYl, WYl);
            u64 t   = add2(p00, p11);
            u64 Axy = fma2(p01, c_ns1, WXYl);
            u64 AB  = fma2(t,   c_ns1, WZl);
            u64 n1  = fma2(p01, c_kn1, c_C1);
            u64 n2  = fma2(Axy, c_kc2, c_C2);
            u64 d1  = fma2(t,   c_ks2, c_C1);
            u64 d2  = fma2(AB,  c_kcv, c_C2);
            u64 num = mul2(n1, n2);
            u64 den = mul2(d1, d2);
            float na, nb, da, db;
            upk2(na, nb, num); upk2(da, db, den);
            u64 rr = pk2(__fdividef(na, da), __fdividef(nb, db));
            accA = fma2(m01, rr, accA);
        }
        {
            u64 p01 = mul2(WXh, WYh);
            u64 p00 = mul2(WXh, WXh);
            u64 p11 = mul2(WYh, WYh);
            u64 t   = add2(p00, p11);
            u64 Axy = fma2(p01, c_ns1, WXYh);
            u64 AB  = fma2(t,   c_ns1, WZh);
            u64 n1  = fma2(p01, c_kn1, c_C1);
            u64 n2  = fma2(Axy, c_kc2, c_C2);
            u64 d1  = fma2(t,   c_ks2, c_C1);
            u64 d2  = fma2(AB,  c_kcv, c_C2);
            u64 num = mul2(n1, n2);
            u64 den = mul2(d1, d2);
            float na, nb, da, db;
            upk2(na, nb, num); upk2(da, db, den);
            u64 rr = pk2(__fdividef(na, da), __fdividef(nb, db));
            accB = fma2(m23, rr, accB);
        }

        // retire leaving row (input r0+r): reload from L1, subtract
        {
            float4 a = *(const float4*)(xp + (size_t)(r0 + r) * IMG_W + cs);
            float4 b = *(const float4*)(yp + (size_t)(r0 + r) * IMG_W + cs);
            u64 ox01 = pk2(a.x, a.y), ox23 = pk2(a.z, a.w);
            u64 oy01 = pk2(b.x, b.y), oy23 = pk2(b.z, b.w);
            u64 nx01 = neg2(ox01), nx23 = neg2(ox23);
            u64 ny01 = neg2(oy01), ny23 = neg2(oy23);
            X01 = add2(X01, nx01);  X23 = add2(X23, nx23);
            Y01 = add2(Y01, ny01);  Y23 = add2(Y23, ny23);
            Z01 = fma2(ox01, nx01, fma2(oy01, ny01, Z01));
            Z23 = fma2(ox23, nx23, fma2(oy23, ny23, Z23));
            XY01 = fma2(ox01, ny01, XY01);  XY23 = fma2(ox23, ny23, XY23);
        }
    }

    // lane-local total, then deterministic warp reduction
    float a0, a1, b0, b1;
    upk2(a0, a1, accA); upk2(b0, b1, accB);
    float acc = (a0 + a1) + (b0 + b1);
    #pragma unroll
    for (int off = 16; off > 0; off >>= 1)
        acc += __shfl_xor_sync(0xffffffffu, acc, off);

    // CTA reduction (deterministic order)
    __shared__ float warp_sums[WARPS_PER_CTA];
    __shared__ unsigned int s_last;
    if (lane == 0) warp_sums[wid] = acc;
    __syncthreads();
    if (threadIdx.x == 0) {
        float c = 0.f;
        #pragma unroll
        for (int i = 0; i < WARPS_PER_CTA; ++i) c += warp_sums[i];
        g_cta[blockIdx.x] = c;
        __threadfence();
        unsigned int old = atomicAdd(&g_done, 1u);
        s_last = (old == NCTA - 1) ? 1u : 0u;
    }
    __syncthreads();

    // last CTA reduces all CTA partials (deterministic order per slot)
    if (s_last) {
        __shared__ float red[256];
        const int t = threadIdx.x;
        float c = g_cta[t] + ((t + 256 < NCTA) ? g_cta[t + 256] : 0.f);
        red[t] = c;
        __syncthreads();
        #pragma unroll
        for (int s = 128; s > 0; s >>= 1) {
            if (t < s) red[t] += red[t + s];
            __syncthreads();
        }
        if (t == 0) {
            out[0] = red[0] * (1.0f / ((float)NIMG * (float)OUT_W * (float)OUT_H));
            g_done = 0;   // reset for next launch / graph replay
        }
    }
}

extern "C" void kernel_launch(void* const* d_in, const int* in_sizes, int n_in,
                              void* d_out, int out_size) {
    const float* pred   = (const float*)d_in[0];
    const float* actual = (const float*)d_in[1];
    float* out = (float*)d_out;

    ssim_v5_kernel<<<NCTA, WARPS_PER_CTA * 32>>>(pred, actual, out);
}

// round 6
// speedup vs baseline: 1.1032x; 1.1032x over previous
#include <cuda_runtime.h>

// SSIM, 7x7 VALID box, 128 x 384x384 fp32 pairs -> scalar mean.
//
// v6: v5's packed-f32x2 pipeline with higher occupancy for latency hiding.
//  - 9 row-bands of 42 (was 6x63): 4608 warps (~31/SM) instead of 3072 (~21/SM).
//  - 128-thread CTAs for finer SM packing under the 56-reg budget.
//  - Everything else identical: 4 cols/lane, Z=XX+YY merged, packed
//    horizontal 7-sums (9 add2 + 6 shfl per quantity), single-kernel
//    deterministic last-CTA reduction.

#define IMG_H 384
#define IMG_W 384
#define OUT_W 378
#define OUT_H 378
#define NIMG  128
#define NSTRIP 4
#define NBAND  9
#define BAND_OUT 42
#define WARPS_PER_CTA 4
#define WARPS_TOTAL (NIMG * NSTRIP * NBAND)      // 4608
#define NCTA (WARPS_TOTAL / WARPS_PER_CTA)       // 1152

__device__ float g_cta[NCTA];
__device__ unsigned int g_done = 0;

typedef unsigned long long u64;
static __device__ __forceinline__ u64 pk2(float lo, float hi) {
    u64 r; asm("mov.b64 %0,{%1,%2};" : "=l"(r) : "f"(lo), "f"(hi)); return r;
}
static __device__ __forceinline__ void upk2(float& lo, float& hi, u64 v) {
    asm("mov.b64 {%0,%1},%2;" : "=f"(lo), "=f"(hi) : "l"(v));
}
static __device__ __forceinline__ u64 add2(u64 a, u64 b) {
    u64 d; asm("add.rn.f32x2 %0,%1,%2;" : "=l"(d) : "l"(a), "l"(b)); return d;
}
static __device__ __forceinline__ u64 mul2(u64 a, u64 b) {
    u64 d; asm("mul.rn.f32x2 %0,%1,%2;" : "=l"(d) : "l"(a), "l"(b)); return d;
}
static __device__ __forceinline__ u64 fma2(u64 a, u64 b, u64 c) {
    u64 d; asm("fma.rn.f32x2 %0,%1,%2,%3;" : "=l"(d) : "l"(a), "l"(b), "l"(c)); return d;
}
static __device__ __forceinline__ u64 neg2(u64 a) {
    return a ^ 0x8000000080000000ULL;
}

#define HPACK(q01, q23, Wlo, Whi)                                          \
    {                                                                      \
        float v0, v1, v2, v3;                                              \
        upk2(v0, v1, q01); upk2(v2, v3, q23);                              \
        float v4 = __shfl_down_sync(0xffffffffu, v0, 1);                   \
        float v5 = __shfl_down_sync(0xffffffffu, v1, 1);                   \
        float v6 = __shfl_down_sync(0xffffffffu, v2, 1);                   \
        float v7 = __shfl_down_sync(0xffffffffu, v3, 1);                   \
        float v8 = __shfl_down_sync(0xffffffffu, v0, 2);                   \
        float v9 = __shfl_down_sync(0xffffffffu, v1, 2);                   \
        u64 E2 = pk2(v4, v5), E3 = pk2(v6, v7), E4 = pk2(v8, v9);          \
        u64 D0 = pk2(v1, v2), D1 = pk2(v3, v4);                            \
        u64 D2 = pk2(v5, v6), D3 = pk2(v7, v8);                            \
        u64 SE = add2(q23, add2(E2, E3));                                  \
        u64 SD = add2(D1, D2);                                             \
        Wlo = add2(add2(q01, SE), add2(D0, SD));                           \
        Whi = add2(add2(SE, E4), add2(SD, D3));                            \
    }

__global__ __launch_bounds__(WARPS_PER_CTA * 32)
void ssim_v6_kernel(const float* __restrict__ pred,
                    const float* __restrict__ actual,
                    float* __restrict__ out) {
    const int gtid = blockIdx.x * blockDim.x + threadIdx.x;
    const int W    = gtid >> 5;
    const int lane = gtid & 31;
    const int wid  = threadIdx.x >> 5;

    const int img   = W / (NSTRIP * NBAND);
    const int rem   = W - img * (NSTRIP * NBAND);
    const int band  = rem / NSTRIP;
    const int strip = rem - band * NSTRIP;

    // strips: [0,96) [96,192) [192,284) [284,378)
    int base = strip * 96;          if (strip == 3) base = 284;
    int send = base + 96;           if (strip == 2) send = 284;
    if (strip == 3) send = 378;

    int cs = base + 4 * lane;
    if (cs > IMG_W - 4) cs = IMG_W - 4;

    const int r0 = band * BAND_OUT;

    const float* __restrict__ xp = pred   + (size_t)img * IMG_H * IMG_W;
    const float* __restrict__ yp = actual + (size_t)img * IMG_H * IMG_W;

    const int oc = base + 4 * lane;
    const u64 m01 = pk2((oc + 0 < send) ? 1.f : 0.f, (oc + 1 < send) ? 1.f : 0.f);
    const u64 m23 = pk2((oc + 2 < send) ? 1.f : 0.f, (oc + 3 < send) ? 1.f : 0.f);

    // packed vertical sliding sums: X, Y, Z = XX+YY, XY
    u64 X01 = 0, X23 = 0, Y01 = 0, Y23 = 0;
    u64 Z01 = 0, Z23 = 0, XY01 = 0, XY23 = 0;

    #pragma unroll 1
    for (int k = 0; k < 6; ++k) {
        float4 a = *(const float4*)(xp + (size_t)(r0 + k) * IMG_W + cs);
        float4 b = *(const float4*)(yp + (size_t)(r0 + k) * IMG_W + cs);
        u64 ax01 = pk2(a.x, a.y), ax23 = pk2(a.z, a.w);
        u64 ay01 = pk2(b.x, b.y), ay23 = pk2(b.z, b.w);
        X01 = add2(X01, ax01);  X23 = add2(X23, ax23);
        Y01 = add2(Y01, ay01);  Y23 = add2(Y23, ay23);
        Z01 = fma2(ax01, ax01, fma2(ay01, ay01, Z01));
        Z23 = fma2(ax23, ax23, fma2(ay23, ay23, Z23));
        XY01 = fma2(ax01, ay01, XY01);  XY23 = fma2(ax23, ay23, XY23);
    }

    float4 pfx = *(const float4*)(xp + (size_t)(r0 + 6) * IMG_W + cs);
    float4 pfy = *(const float4*)(yp + (size_t)(r0 + 6) * IMG_W + cs);

    const float s1   = 1.0f / 49.0f;
    const float covn = 49.0f / 48.0f;
    const u64 c_ns1 = pk2(-s1, -s1);
    const u64 c_kn1 = pk2(2.f * s1 * s1, 2.f * s1 * s1);
    const u64 c_ks2 = pk2(s1 * s1, s1 * s1);
    const u64 c_kcv = pk2(covn * s1, covn * s1);
    const u64 c_kc2 = pk2(2.f * covn * s1, 2.f * covn * s1);
    const u64 c_C1  = pk2(1e-4f, 1e-4f);
    const u64 c_C2  = pk2(9e-4f, 9e-4f);

    u64 accA = 0, accB = 0;

    #pragma unroll 1
    for (int r = 0; r < BAND_OUT; ++r) {
        // admit prefetched row (input r0+r+6)
        {
            u64 ax01 = pk2(pfx.x, pfx.y), ax23 = pk2(pfx.z, pfx.w);
            u64 ay01 = pk2(pfy.x, pfy.y), ay23 = pk2(pfy.z, pfy.w);
            X01 = add2(X01, ax01);  X23 = add2(X23, ax23);
            Y01 = add2(Y01, ay01);  Y23 = add2(Y23, ay23);
            Z01 = fma2(ax01, ax01, fma2(ay01, ay01, Z01));
            Z23 = fma2(ax23, ax23, fma2(ay23, ay23, Z23));
            XY01 = fma2(ax01, ay01, XY01);  XY23 = fma2(ax23, ay23, XY23);
        }
        // prefetch next row (clamped)
        {
            int nr = min(r0 + r + 7, IMG_H - 1);
            pfx = *(const float4*)(xp + (size_t)nr * IMG_W + cs);
            pfy = *(const float4*)(yp + (size_t)nr * IMG_W + cs);
        }

        // horizontal packed 7-sums
        u64 WXl, WXh, WYl, WYh, WZl, WZh, WXYl, WXYh;
        HPACK(X01,  X23,  WXl,  WXh);
        HPACK(Y01,  Y23,  WYl,  WYh);
        HPACK(Z01,  Z23,  WZl,  WZh);
        HPACK(XY01, XY23, WXYl, WXYh);

        // SSIM, packed halves
        {
            u64 p01 = mul2(WXl, WYl);
            u64 p00 = mul2(WXl, WXl);
            u64 p11 = mul2(WYl, WYl);
            u64 t   = add2(p00, p11);
            u64 Axy = fma2(p01, c_ns1, WXYl);
            u64 AB  = fma2(t,   c_ns1, WZl);
            u64 n1  = fma2(p01, c_kn1, c_C1);
            u64 n2  = fma2(Axy, c_kc2, c_C2);
            u64 d1  = fma2(t,   c_ks2, c_C1);
            u64 d2  = fma2(AB,  c_kcv, c_C2);
            u64 num = mul2(n1, n2);
            u64 den = mul2(d1, d2);
            float na, nb, da, db;
            upk2(na, nb, num); upk2(da, db, den);
            u64 rr = pk2(__fdividef(na, da), __fdividef(nb, db));
            accA = fma2(m01, rr, accA);
        }
        {
            u64 p01 = mul2(WXh, WYh);
            u64 p00 = mul2(WXh, WXh);
            u64 p11 = mul2(WYh, WYh);
            u64 t   = add2(p00, p11);
            u64 Axy = fma2(p01, c_ns1, WXYh);
            u64 AB  = fma2(t,   c_ns1, WZh);
            u64 n1  = fma2(p01, c_kn1, c_C1);
            u64 n2  = fma2(Axy, c_kc2, c_C2);
            u64 d1  = fma2(t,   c_ks2, c_C1);
            u64 d2  = fma2(AB,  c_kcv, c_C2);
            u64 num = mul2(n1, n2);
            u64 den = mul2(d1, d2);
            float na, nb, da, db;
            upk2(na, nb, num); upk2(da, db, den);
            u64 rr = pk2(__fdividef(na, da), __fdividef(nb, db));
            accB = fma2(m23, rr, accB);
        }

        // retire leaving row (input r0+r): reload from L1, subtract
        {
            float4 a = *(const float4*)(xp + (size_t)(r0 + r) * IMG_W + cs);
            float4 b = *(const float4*)(yp + (size_t)(r0 + r) * IMG_W + cs);
            u64 ox01 = pk2(a.x, a.y), ox23 = pk2(a.z, a.w);
            u64 oy01 = pk2(b.x, b.y), oy23 = pk2(b.z, b.w);
            u64 nx01 = neg2(ox01), nx23 = neg2(ox23);
            u64 ny01 = neg2(oy01), ny23 = neg2(oy23);
            X01 = add2(X01, nx01);  X23 = add2(X23, nx23);
            Y01 = add2(Y01, ny01);  Y23 = add2(Y23, ny23);
            Z01 = fma2(ox01, nx01, fma2(oy01, ny01, Z01));
            Z23 = fma2(ox23, nx23, fma2(oy23, ny23, Z23));
            XY01 = fma2(ox01, ny01, XY01);  XY23 = fma2(ox23, ny23, XY23);
        }
    }

    // lane-local total, then deterministic warp reduction
    float a0, a1, b0, b1;
    upk2(a0, a1, accA); upk2(b0, b1, accB);
    float acc = (a0 + a1) + (b0 + b1);
    #pragma unroll
    for (int off = 16; off > 0; off >>= 1)
        acc += __shfl_xor_sync(0xffffffffu, acc, off);

    // CTA reduction (deterministic order)
    __shared__ float warp_sums[WARPS_PER_CTA];
    __shared__ unsigned int s_last;
    if (lane == 0) warp_sums[wid] = acc;
    __syncthreads();
    if (threadIdx.x == 0) {
        float c = 0.f;
        #pragma unroll
        for (int i = 0; i < WARPS_PER_CTA; ++i) c += warp_sums[i];
        g_cta[blockIdx.x] = c;
        __threadfence();
        unsigned int old = atomicAdd(&g_done, 1u);
        s_last = (old == NCTA - 1) ? 1u : 0u;
    }
    __syncthreads();

    // last CTA reduces all CTA partials (deterministic per-slot order)
    if (s_last) {
        __shared__ float red[128];
        const int t = threadIdx.x;
        float c = 0.f;
        #pragma unroll
        for (int i = 0; i < NCTA / 128; ++i)   // 9 slots per thread, fixed order
            c += g_cta[t + i * 128];
        red[t] = c;
        __syncthreads();
        #pragma unroll
        for (int s = 64; s > 0; s >>= 1) {
            if (t < s) red[t] += red[t + s];
            __syncthreads();
        }
        if (t == 0) {
            out[0] = red[0] * (1.0f / ((float)NIMG * (float)OUT_W * (float)OUT_H));
            g_done = 0;   // reset for graph replay
        }
    }
}

extern "C" void kernel_launch(void* const* d_in, const int* in_sizes, int n_in,
                              void* d_out, int out_size) {
    const float* pred   = (const float*)d_in[0];
    const float* actual = (const float*)d_in[1];
    float* out = (float*)d_out;

    ssim_v6_kernel<<<NCTA, WARPS_PER_CTA * 32>>>(pred, actual, out);
}

// round 7
// speedup vs baseline: 1.2008x; 1.0885x over previous
#include <cuda_runtime.h>

// SSIM, 7x7 VALID box, 128 x 384x384 fp32 pairs -> scalar mean.
//
// v7: v6 + intra-warp ILP.
//  - Two output rows per loop iteration: two independent horizontal+SSIM
//    chains in flight per warp.
//  - Pointer-increment addressing: all row offsets are LDG immediates.
//  - Retire-row loads hoisted to iteration top (latency overlapped).
//  - Same packed-f32x2 math, 9 bands x 42 rows, 4-warp CTAs, single-kernel
//    deterministic last-CTA reduction.

#define IMG_H 384
#define IMG_W 384
#define OUT_W 378
#define OUT_H 378
#define NIMG  128
#define NSTRIP 4
#define NBAND  9
#define BAND_OUT 42
#define WARPS_PER_CTA 4
#define WARPS_TOTAL (NIMG * NSTRIP * NBAND)      // 4608
#define NCTA (WARPS_TOTAL / WARPS_PER_CTA)       // 1152

__device__ float g_cta[NCTA];
__device__ unsigned int g_done = 0;

typedef unsigned long long u64;
static __device__ __forceinline__ u64 pk2(float lo, float hi) {
    u64 r; asm("mov.b64 %0,{%1,%2};" : "=l"(r) : "f"(lo), "f"(hi)); return r;
}
static __device__ __forceinline__ void upk2(float& lo, float& hi, u64 v) {
    asm("mov.b64 {%0,%1},%2;" : "=f"(lo), "=f"(hi) : "l"(v));
}
static __device__ __forceinline__ u64 add2(u64 a, u64 b) {
    u64 d; asm("add.rn.f32x2 %0,%1,%2;" : "=l"(d) : "l"(a), "l"(b)); return d;
}
static __device__ __forceinline__ u64 mul2(u64 a, u64 b) {
    u64 d; asm("mul.rn.f32x2 %0,%1,%2;" : "=l"(d) : "l"(a), "l"(b)); return d;
}
static __device__ __forceinline__ u64 fma2(u64 a, u64 b, u64 c) {
    u64 d; asm("fma.rn.f32x2 %0,%1,%2,%3;" : "=l"(d) : "l"(a), "l"(b), "l"(c)); return d;
}
static __device__ __forceinline__ u64 neg2(u64 a) {
    return a ^ 0x8000000080000000ULL;
}

#define HPACK(q01, q23, Wlo, Whi)                                          \
    {                                                                      \
        float v0, v1, v2, v3;                                              \
        upk2(v0, v1, q01); upk2(v2, v3, q23);                              \
        float v4 = __shfl_down_sync(0xffffffffu, v0, 1);                   \
        float v5 = __shfl_down_sync(0xffffffffu, v1, 1);                   \
        float v6 = __shfl_down_sync(0xffffffffu, v2, 1);                   \
        float v7 = __shfl_down_sync(0xffffffffu, v3, 1);                   \
        float v8 = __shfl_down_sync(0xffffffffu, v0, 2);                   \
        float v9 = __shfl_down_sync(0xffffffffu, v1, 2);                   \
        u64 E2 = pk2(v4, v5), E3 = pk2(v6, v7), E4 = pk2(v8, v9);          \
        u64 D0 = pk2(v1, v2), D1 = pk2(v3, v4);                            \
        u64 D2 = pk2(v5, v6), D3 = pk2(v7, v8);                            \
        u64 SE = add2(q23, add2(E2, E3));                                  \
        u64 SD = add2(D1, D2);                                             \
        Wlo = add2(add2(q01, SE), add2(D0, SD));                           \
        Whi = add2(add2(SE, E4), add2(SD, D3));                            \
    }

// admit packed row (a4,b4 are float4 of x and y)
#define ADMIT(a4, b4)                                                      \
    {                                                                      \
        u64 ax01 = pk2((a4).x, (a4).y), ax23 = pk2((a4).z, (a4).w);        \
        u64 ay01 = pk2((b4).x, (b4).y), ay23 = pk2((b4).z, (b4).w);        \
        X01 = add2(X01, ax01);  X23 = add2(X23, ax23);                     \
        Y01 = add2(Y01, ay01);  Y23 = add2(Y23, ay23);                     \
        Z01 = fma2(ax01, ax01, fma2(ay01, ay01, Z01));                     \
        Z23 = fma2(ax23, ax23, fma2(ay23, ay23, Z23));                     \
        XY01 = fma2(ax01, ay01, XY01);  XY23 = fma2(ax23, ay23, XY23);     \
    }

#define RETIRE(a4, b4)                                                     \
    {                                                                      \
        u64 ox01 = pk2((a4).x, (a4).y), ox23 = pk2((a4).z, (a4).w);        \
        u64 oy01 = pk2((b4).x, (b4).y), oy23 = pk2((b4).z, (b4).w);        \
        u64 nx01 = neg2(ox01), nx23 = neg2(ox23);                          \
        u64 ny01 = neg2(oy01), ny23 = neg2(oy23);                          \
        X01 = add2(X01, nx01);  X23 = add2(X23, nx23);                     \
        Y01 = add2(Y01, ny01);  Y23 = add2(Y23, ny23);                     \
        Z01 = fma2(ox01, nx01, fma2(oy01, ny01, Z01));                     \
        Z23 = fma2(ox23, nx23, fma2(oy23, ny23, Z23));                     \
        XY01 = fma2(ox01, ny01, XY01);  XY23 = fma2(ox23, ny23, XY23);     \
    }

#define SSIM_HALF(WX, WY, WZ, WXY, mask, accR)                             \
    {                                                                      \
        u64 p01 = mul2(WX, WY);                                            \
        u64 p00 = mul2(WX, WX);                                            \
        u64 p11 = mul2(WY, WY);                                            \
        u64 tt  = add2(p00, p11);                                          \
        u64 Axy = fma2(p01, c_ns1, WXY);                                   \
        u64 AB  = fma2(tt,  c_ns1, WZ);                                    \
        u64 n1  = fma2(p01, c_kn1, c_C1);                                  \
        u64 n2  = fma2(Axy, c_kc2, c_C2);                                  \
        u64 d1  = fma2(tt,  c_ks2, c_C1);                                  \
        u64 d2  = fma2(AB,  c_kcv, c_C2);                                  \
        u64 num = mul2(n1, n2);                                            \
        u64 den = mul2(d1, d2);                                            \
        float na, nb, da, db;                                              \
        upk2(na, nb, num); upk2(da, db, den);                              \
        u64 rr = pk2(__fdividef(na, da), __fdividef(nb, db));              \
        accR = fma2(mask, rr, accR);                                       \
    }

#define DO_ROW()                                                           \
    {                                                                      \
        u64 WXl, WXh, WYl, WYh, WZl, WZh, WXYl, WXYh;                      \
        HPACK(X01,  X23,  WXl,  WXh);                                      \
        HPACK(Y01,  Y23,  WYl,  WYh);                                      \
        HPACK(Z01,  Z23,  WZl,  WZh);                                      \
        HPACK(XY01, XY23, WXYl, WXYh);                                     \
        SSIM_HALF(WXl, WYl, WZl, WXYl, m01, accA);                         \
        SSIM_HALF(WXh, WYh, WZh, WXYh, m23, accB);                         \
    }

__global__ __launch_bounds__(WARPS_PER_CTA * 32)
void ssim_v7_kernel(const float* __restrict__ pred,
                    const float* __restrict__ actual,
                    float* __restrict__ out) {
    const int gtid = blockIdx.x * blockDim.x + threadIdx.x;
    const int W    = gtid >> 5;
    const int lane = gtid & 31;
    const int wid  = threadIdx.x >> 5;

    const int img   = W / (NSTRIP * NBAND);
    const int rem   = W - img * (NSTRIP * NBAND);
    const int band  = rem / NSTRIP;
    const int strip = rem - band * NSTRIP;

    // strips: [0,96) [96,192) [192,284) [284,378)
    int base = strip * 96;          if (strip == 3) base = 284;
    int send = base + 96;           if (strip == 2) send = 284;
    if (strip == 3) send = 378;

    int cs = base + 4 * lane;
    if (cs > IMG_W - 4) cs = IMG_W - 4;

    const int r0 = band * BAND_OUT;

    const int oc = base + 4 * lane;
    const u64 m01 = pk2((oc + 0 < send) ? 1.f : 0.f, (oc + 1 < send) ? 1.f : 0.f);
    const u64 m23 = pk2((oc + 2 < send) ? 1.f : 0.f, (oc + 3 < send) ? 1.f : 0.f);

    // walking pointers at row r (current retire row)
    const float* pX = pred   + (size_t)img * IMG_H * IMG_W + (size_t)r0 * IMG_W + cs;
    const float* pY = actual + (size_t)img * IMG_H * IMG_W + (size_t)r0 * IMG_W + cs;

    // packed vertical sliding sums
    u64 X01 = 0, X23 = 0, Y01 = 0, Y23 = 0;
    u64 Z01 = 0, Z23 = 0, XY01 = 0, XY23 = 0;

    // prologue: rows r0..r0+5
    #pragma unroll 1
    for (int k = 0; k < 6; ++k) {
        float4 a = *(const float4*)(pX + (size_t)k * IMG_W);
        float4 b = *(const float4*)(pY + (size_t)k * IMG_W);
        ADMIT(a, b);
    }

    // prefetch rows r0+6, r0+7
    float4 pfAx = *(const float4*)(pX + (size_t)6 * IMG_W);
    float4 pfAy = *(const float4*)(pY + (size_t)6 * IMG_W);
    float4 pfBx = *(const float4*)(pX + (size_t)7 * IMG_W);
    float4 pfBy = *(const float4*)(pY + (size_t)7 * IMG_W);

    const float s1   = 1.0f / 49.0f;
    const float covn = 49.0f / 48.0f;
    const u64 c_ns1 = pk2(-s1, -s1);
    const u64 c_kn1 = pk2(2.f * s1 * s1, 2.f * s1 * s1);
    const u64 c_ks2 = pk2(s1 * s1, s1 * s1);
    const u64 c_kcv = pk2(covn * s1, covn * s1);
    const u64 c_kc2 = pk2(2.f * covn * s1, 2.f * covn * s1);
    const u64 c_C1  = pk2(1e-4f, 1e-4f);
    const u64 c_C2  = pk2(9e-4f, 9e-4f);

    u64 accA = 0, accB = 0;

    // 20 iterations x 2 rows (rows 0..39), then 2-row epilogue (rows 40,41).
    // Max prefetch row: r0 + 2*19 + 9 = r0 + 47 <= 383 for all bands.
    #pragma unroll 1
    for (int it = 0; it < (BAND_OUT - 2) / 2; ++it) {
        float4 rt0x = *(const float4*)(pX);
        float4 rt0y = *(const float4*)(pY);
        float4 rt1x = *(const float4*)(pX + IMG_W);
        float4 rt1y = *(const float4*)(pY + IMG_W);

        ADMIT(pfAx, pfAy);         // window complete for row r
        DO_ROW();
        RETIRE(rt0x, rt0y);
        ADMIT(pfBx, pfBy);         // window complete for row r+1
        DO_ROW();
        RETIRE(rt1x, rt1y);

        pfAx = *(const float4*)(pX + (size_t)8 * IMG_W);
        pfAy = *(const float4*)(pY + (size_t)8 * IMG_W);
        pfBx = *(const float4*)(pX + (size_t)9 * IMG_W);
        pfBy = *(const float4*)(pY + (size_t)9 * IMG_W);

        pX += 2 * IMG_W;  pY += 2 * IMG_W;
    }
    // epilogue rows BAND_OUT-2, BAND_OUT-1
    {
        float4 rt0x = *(const float4*)(pX);
        float4 rt0y = *(const float4*)(pY);
        ADMIT(pfAx, pfAy);
        DO_ROW();
        RETIRE(rt0x, rt0y);
        ADMIT(pfBx, pfBy);
        DO_ROW();
    }

    // lane-local total, deterministic warp reduction
    float a0, a1, b0, b1;
    upk2(a0, a1, accA); upk2(b0, b1, accB);
    float acc = (a0 + a1) + (b0 + b1);
    #pragma unroll
    for (int off = 16; off > 0; off >>= 1)
        acc += __shfl_xor_sync(0xffffffffu, acc, off);

    // CTA reduction (deterministic order)
    __shared__ float warp_sums[WARPS_PER_CTA];
    __shared__ unsigned int s_last;
    if (lane == 0) warp_sums[wid] = acc;
    __syncthreads();
    if (threadIdx.x == 0) {
        float c = 0.f;
        #pragma unroll
        for (int i = 0; i < WARPS_PER_CTA; ++i) c += warp_sums[i];
        g_cta[blockIdx.x] = c;
        __threadfence();
        unsigned int old = atomicAdd(&g_done, 1u);
        s_last = (old == NCTA - 1) ? 1u : 0u;
    }
    __syncthreads();

    if (s_last) {
        __shared__ float red[128];
        const int t = threadIdx.x;
        float c = 0.f;
        #pragma unroll
        for (int i = 0; i < NCTA / 128; ++i)
            c += g_cta[t + i * 128];
        red[t] = c;
        __syncthreads();
        #pragma unroll
        for (int s = 64; s > 0; s >>= 1) {
            if (t < s) red[t] += red[t + s];
            __syncthreads();
        }
        if (t == 0) {
            out[0] = red[0] * (1.0f / ((float)NIMG * (float)OUT_W * (float)OUT_H));
            g_done = 0;   // reset for graph replay
        }
    }
}

extern "C" void kernel_launch(void* const* d_in, const int* in_sizes, int n_in,
                              void* d_out, int out_size) {
    const float* pred   = (const float*)d_in[0];
    const float* actual = (const float*)d_in[1];
    float* out = (float*)d_out;

    ssim_v7_kernel<<<NCTA, WARPS_PER_CTA * 32>>>(pred, actual, out);
}